// round 1
// baseline (speedup 1.0000x reference)
#include <cuda_runtime.h>
#include <math.h>

#define NPTS   4096
#define NB     16
#define NARR   32           // 16 batches x 2 directions
#define D      3
#define NEL    (NPTS * D)   // 12288 residual elements per array
#define NSORT  16384        // next pow2 >= NEL
#define TILE   2048         // targets per smem tile

// Scratch (device globals only; no allocation allowed)
__device__ float g_resid[(size_t)NARR * NEL];
__device__ float g_sigma[NARR];

// ---------------------------------------------------------------------------
// Kernel A: brute-force nearest-neighbor residuals.
// For array arr = 2*batch + dir: queries = (dir==0 ? x[b] : y[b]),
// targets = the other set. Writes residual (a - b_nn) per query, 3 floats.
// ---------------------------------------------------------------------------
__global__ __launch_bounds__(128) void nn_resid_kernel(
    const float* __restrict__ x, const float* __restrict__ y)
{
    const int arr   = blockIdx.y;          // 0..31
    const int batch = arr >> 1;
    const int dir   = arr & 1;
    const float* Qp = (dir == 0) ? (x + (size_t)batch * NPTS * D)
                                 : (y + (size_t)batch * NPTS * D);
    const float* Tp = (dir == 0) ? (y + (size_t)batch * NPTS * D)
                                 : (x + (size_t)batch * NPTS * D);

    __shared__ float4 sb[TILE];            // {bx, by, bz, -0.5*|b|^2}  32KB

    const int tid = threadIdx.x;           // 128 threads
    const int QN  = 2;                     // queries per thread
    const int qbase = blockIdx.x * (128 * QN);

    float ax[QN], ay[QN], az[QN];
    float best[QN];
    int   bidx[QN];
#pragma unroll
    for (int q = 0; q < QN; q++) {
        int qi = qbase + tid + q * 128;
        ax[q] = Qp[3 * qi + 0];
        ay[q] = Qp[3 * qi + 1];
        az[q] = Qp[3 * qi + 2];
        best[q] = -1e30f;
        bidx[q] = 0;
    }

    for (int t = 0; t < NPTS; t += TILE) {
        __syncthreads();
        for (int i = tid; i < TILE; i += 128) {
            const float* p = Tp + 3 * (size_t)(t + i);
            float bx = p[0], by = p[1], bz = p[2];
            sb[i] = make_float4(bx, by, bz,
                                -0.5f * (bx * bx + by * by + bz * bz));
        }
        __syncthreads();

#pragma unroll 4
        for (int m = 0; m < TILE; m++) {
            float4 b = sb[m];
#pragma unroll
            for (int q = 0; q < QN; q++) {
                // maximize a.b - 0.5|b|^2  <=>  minimize |a-b|^2
                float s = fmaf(ax[q], b.x, fmaf(ay[q], b.y, fmaf(az[q], b.z, b.w)));
                if (s > best[q]) { best[q] = s; bidx[q] = t + m; }
            }
        }
    }

#pragma unroll
    for (int q = 0; q < QN; q++) {
        int qi = qbase + tid + q * 128;
        const float* p = Tp + 3 * (size_t)bidx[q];
        float* r = g_resid + (size_t)arr * NEL + 3 * (size_t)qi;
        r[0] = ax[q] - p[0];
        r[1] = ay[q] - p[1];
        r[2] = az[q] - p[2];
    }
}

// ---------------------------------------------------------------------------
// Block reduction helper (sum to all threads). Block-uniform call sites only.
// ---------------------------------------------------------------------------
__device__ __forceinline__ float blockReduceSumF(float v, float* sbuf, int tid)
{
#pragma unroll
    for (int o = 16; o; o >>= 1) v += __shfl_down_sync(0xffffffffu, v, o);
    if ((tid & 31) == 0) sbuf[tid >> 5] = v;
    __syncthreads();
    if (tid < 32) {
        float w = sbuf[tid];                 // 1024 threads -> exactly 32 warps
#pragma unroll
        for (int o = 16; o; o >>= 1) w += __shfl_down_sync(0xffffffffu, w, o);
        if (tid == 0) sbuf[0] = w;
    }
    __syncthreads();
    float r = sbuf[0];
    __syncthreads();
    return r;
}

// ---------------------------------------------------------------------------
// Kernel B: per-array robust masked std.
// Bitonic sort 12288 values (padded to 16384 with +inf) in dynamic smem,
// jnp.quantile(linear) at q=0.15/0.85, quantile-outlier mask (Z_INDEX=0),
// fallback: simple |x-mu|>sd mask, then all-ones. Unbiased variance.
// ---------------------------------------------------------------------------
__global__ __launch_bounds__(1024) void robust_std_kernel()
{
    extern __shared__ float sm[];            // NSORT floats = 64KB
    __shared__ float sbuf[32];

    const int arr = blockIdx.x;
    const int tid = threadIdx.x;
    const int T   = 1024;
    const float* src = g_resid + (size_t)arr * NEL;

    const float INF = __int_as_float(0x7f800000);
    for (int i = tid; i < NSORT; i += T)
        sm[i] = (i < NEL) ? src[i] : INF;
    __syncthreads();

    // Bitonic sort, ascending. Pairs are disjoint per (k,j) stage.
    for (int k = 2; k <= NSORT; k <<= 1) {
        for (int j = k >> 1; j > 0; j >>= 1) {
            for (int i = tid; i < NSORT; i += T) {
                int l = i ^ j;
                if (l > i) {
                    float a = sm[i], b = sm[l];
                    bool up = ((i & k) == 0);
                    if ((a > b) == up) { sm[i] = b; sm[l] = a; }
                }
            }
            __syncthreads();
        }
    }

    // Quantiles (numpy/jnp "linear" interpolation), float32 arithmetic.
    const float n1 = (float)(NEL - 1);
    float hlo = 0.15f * n1;
    int   ilo = (int)hlo;
    float flo = hlo - (float)ilo;
    float qlo = sm[ilo] + flo * (sm[ilo + 1] - sm[ilo]);
    float hhi = 0.85f * n1;
    int   ihi = (int)hhi;
    float fhi = hhi - (float)ihi;
    float qhi = sm[ihi] + fhi * (sm[ihi + 1] - sm[ihi]);

    // Pass 1: quantile-outlier mask count + sum (Z_INDEX = 0 -> thresholds = q).
    float lc = 0.f, ls = 0.f;
    for (int i = tid; i < NEL; i += T) {
        float v = sm[i];
        if (v < qlo || v > qhi) { lc += 1.f; ls += v; }
    }
    float cnt = blockReduceSumF(lc, sbuf, tid);
    float sum = blockReduceSumF(ls, sbuf, tid);

    int mode = 0;                 // 0=quantile mask, 1=simple mask, 2=all
    float muA = 0.f, sdA = 0.f;
    if (cnt < 0.5f) {
        float la = 0.f;
        for (int i = tid; i < NEL; i += T) la += sm[i];
        float sumA = blockReduceSumF(la, sbuf, tid);
        muA = sumA / (float)NEL;
        float lq = 0.f;
        for (int i = tid; i < NEL; i += T) {
            float d = sm[i] - muA; lq += d * d;
        }
        float ssA = blockReduceSumF(lq, sbuf, tid);
        sdA = sqrtf(ssA / (float)(NEL - 1));   // unbiased (torch.std)
        lc = 0.f; ls = 0.f;
        for (int i = tid; i < NEL; i += T) {
            float v = sm[i];
            if (fabsf(v - muA) > sdA) { lc += 1.f; ls += v; }
        }
        cnt = blockReduceSumF(lc, sbuf, tid);
        sum = blockReduceSumF(ls, sbuf, tid);
        mode = 1;
        if (cnt < 0.5f) { mode = 2; cnt = (float)NEL; sum = sumA; }
    }

    float mean = sum / cnt;
    float lss = 0.f;
    for (int i = tid; i < NEL; i += T) {
        float v = sm[i];
        bool w = (mode == 0) ? (v < qlo || v > qhi)
               : (mode == 1) ? (fabsf(v - muA) > sdA)
               : true;
        if (w) { float d = v - mean; lss += d * d; }
    }
    float ssd = blockReduceSumF(lss, sbuf, tid);

    if (tid == 0)
        g_sigma[arr] = sqrtf(ssd / (cnt - 1.0f));
}

// ---------------------------------------------------------------------------
// Kernel C: out = mean_b max(sigma[2b], sigma[2b+1])
// ---------------------------------------------------------------------------
__global__ void finalize_kernel(float* __restrict__ out)
{
    int tid = threadIdx.x;                    // 32 threads
    float v = 0.f;
    if (tid < NB) v = fmaxf(g_sigma[2 * tid], g_sigma[2 * tid + 1]);
#pragma unroll
    for (int o = 16; o; o >>= 1) v += __shfl_down_sync(0xffffffffu, v, o);
    if (tid == 0) out[0] = v * (1.0f / (float)NB);
}

// ---------------------------------------------------------------------------
extern "C" void kernel_launch(void* const* d_in, const int* in_sizes, int n_in,
                              void* d_out, int out_size)
{
    const float* x = (const float*)d_in[0];
    const float* y = (const float*)d_in[1];
    float* out = (float*)d_out;
    (void)in_sizes; (void)n_in; (void)out_size;

    // 16 query-chunks of 256 per array, 32 arrays
    dim3 gridA(16, NARR);
    nn_resid_kernel<<<gridA, 128>>>(x, y);

    // 64KB dynamic smem for the sort (host-side attribute set; not a stream op)
    cudaFuncSetAttribute(robust_std_kernel,
                         cudaFuncAttributeMaxDynamicSharedMemorySize,
                         NSORT * (int)sizeof(float));
    robust_std_kernel<<<NARR, 1024, NSORT * sizeof(float)>>>();

    finalize_kernel<<<1, 32>>>(out);
}

// round 2
// speedup vs baseline: 1.7192x; 1.7192x over previous
#include <cuda_runtime.h>
#include <math.h>

#define NPTS   4096
#define NB     16
#define NARR   32           // 16 batches x 2 directions
#define D      3
#define NEL    (NPTS * D)   // 12288 residual elements per array
#define TILE   2048         // targets per smem tile
#define NPAIR  (TILE / 2)

// Scratch (device globals only; no allocation allowed)
__device__ float g_resid[(size_t)NARR * NEL];
__device__ float g_sigma[NARR];

// ---------------------------------------------------------------------------
// f32x2 packed helpers (sm_103a). Bitwise-identical rounding to scalar FFMA.
// ---------------------------------------------------------------------------
__device__ __forceinline__ unsigned long long ffma2_u(
    unsigned long long a, unsigned long long b, unsigned long long c)
{
    unsigned long long d;
    asm("fma.rn.f32x2 %0, %1, %2, %3;" : "=l"(d) : "l"(a), "l"(b), "l"(c));
    return d;
}
__device__ __forceinline__ unsigned long long pack2(float lo, float hi)
{
    unsigned long long r;
    asm("mov.b64 %0, {%1, %2};" : "=l"(r) : "f"(lo), "f"(hi));
    return r;
}
__device__ __forceinline__ void unpack2(unsigned long long v, float& lo, float& hi)
{
    asm("mov.b64 {%0, %1}, %2;" : "=f"(lo), "=f"(hi) : "l"(v));
}

// ---------------------------------------------------------------------------
// Kernel A: brute-force NN residuals, f32x2 packed scores.
// Maximize s = a.b - 0.5|b|^2  <=>  minimize |a-b|^2. Same fma order as R1.
// ---------------------------------------------------------------------------
__global__ __launch_bounds__(128) void nn_resid_kernel(
    const float* __restrict__ x, const float* __restrict__ y)
{
    const int arr   = blockIdx.y;          // 0..31
    const int batch = arr >> 1;
    const int dir   = arr & 1;
    const float* Qp = (dir == 0) ? (x + (size_t)batch * NPTS * D)
                                 : (y + (size_t)batch * NPTS * D);
    const float* Tp = (dir == 0) ? (y + (size_t)batch * NPTS * D)
                                 : (x + (size_t)batch * NPTS * D);

    // pair-interleaved target tiles: sxy[p]={x0,x1,y0,y1}, szw[p]={z0,z1,w0,w1}
    __shared__ float4 sxy[NPAIR];
    __shared__ float4 szw[NPAIR];

    const int tid = threadIdx.x;           // 128 threads
    const int QN  = 2;
    const int qbase = blockIdx.x * (128 * QN);

    unsigned long long axx[QN], ayy[QN], azz[QN];
    float ax[QN], ay[QN], az[QN];
    float best[QN];
    int   bidx[QN];
#pragma unroll
    for (int q = 0; q < QN; q++) {
        int qi = qbase + tid + q * 128;
        ax[q] = Qp[3 * qi + 0];
        ay[q] = Qp[3 * qi + 1];
        az[q] = Qp[3 * qi + 2];
        axx[q] = pack2(ax[q], ax[q]);
        ayy[q] = pack2(ay[q], ay[q]);
        azz[q] = pack2(az[q], az[q]);
        best[q] = -1e30f;
        bidx[q] = 0;
    }

    for (int t = 0; t < NPTS; t += TILE) {
        __syncthreads();
        for (int p = tid; p < NPAIR; p += 128) {
            const float* p0 = Tp + 3 * (size_t)(t + 2 * p);
            float x0 = p0[0], y0 = p0[1], z0 = p0[2];
            float x1 = p0[3], y1 = p0[4], z1 = p0[5];
            float w0 = -0.5f * (x0 * x0 + y0 * y0 + z0 * z0);
            float w1 = -0.5f * (x1 * x1 + y1 * y1 + z1 * z1);
            sxy[p] = make_float4(x0, x1, y0, y1);
            szw[p] = make_float4(z0, z1, w0, w1);
        }
        __syncthreads();

#pragma unroll 4
        for (int p = 0; p < NPAIR; p++) {
            float4 f0 = sxy[p];
            float4 f1 = szw[p];
            unsigned long long bxx = pack2(f0.x, f0.y);
            unsigned long long byy = pack2(f0.z, f0.w);
            unsigned long long bzz = pack2(f1.x, f1.y);
            unsigned long long bww = pack2(f1.z, f1.w);
            int m0 = t + 2 * p;
            int m1 = m0 + 1;
#pragma unroll
            for (int q = 0; q < QN; q++) {
                unsigned long long s2 =
                    ffma2_u(axx[q], bxx, ffma2_u(ayy[q], byy,
                            ffma2_u(azz[q], bzz, bww)));
                float slo, shi;
                unpack2(s2, slo, shi);
                bool c0 = slo > best[q];
                best[q] = c0 ? slo : best[q];
                bidx[q] = c0 ? m0  : bidx[q];
                bool c1 = shi > best[q];
                best[q] = c1 ? shi : best[q];
                bidx[q] = c1 ? m1  : bidx[q];
            }
        }
    }

#pragma unroll
    for (int q = 0; q < QN; q++) {
        int qi = qbase + tid + q * 128;
        const float* p = Tp + 3 * (size_t)bidx[q];
        float* r = g_resid + (size_t)arr * NEL + 3 * (size_t)qi;
        r[0] = ax[q] - p[0];
        r[1] = ay[q] - p[1];
        r[2] = az[q] - p[2];
    }
}

// ---------------------------------------------------------------------------
// Block reductions for 512 threads (16 warps)
// ---------------------------------------------------------------------------
__device__ __forceinline__ float blockSum512(float v, float* sb, int tid)
{
#pragma unroll
    for (int o = 16; o; o >>= 1) v += __shfl_down_sync(0xffffffffu, v, o);
    if ((tid & 31) == 0) sb[tid >> 5] = v;
    __syncthreads();
    if (tid < 32) {
        float w = (tid < 16) ? sb[tid] : 0.f;
#pragma unroll
        for (int o = 8; o; o >>= 1) w += __shfl_down_sync(0xffffffffu, w, o);
        if (tid == 0) sb[0] = w;
    }
    __syncthreads();
    float r = sb[0];
    __syncthreads();
    return r;
}

__device__ __forceinline__ unsigned int blockMin512(unsigned int v,
                                                    unsigned int* sb, int tid)
{
#pragma unroll
    for (int o = 16; o; o >>= 1)
        v = min(v, __shfl_down_sync(0xffffffffu, v, o));
    if ((tid & 31) == 0) sb[tid >> 5] = v;
    __syncthreads();
    if (tid < 32) {
        unsigned int w = (tid < 16) ? sb[tid] : 0xFFFFFFFFu;
#pragma unroll
        for (int o = 8; o; o >>= 1)
            w = min(w, __shfl_down_sync(0xffffffffu, w, o));
        if (tid == 0) sb[0] = w;
    }
    __syncthreads();
    unsigned int r = sb[0];
    __syncthreads();
    return r;
}

// ---------------------------------------------------------------------------
// Kernel B: per-array robust masked std via radix-select quantiles.
// uv[] holds order-preserving uint keys of the residuals in dynamic smem.
// ---------------------------------------------------------------------------
__device__ __forceinline__ float key_to_float(unsigned int u)
{
    u = (u & 0x80000000u) ? (u ^ 0x80000000u) : ~u;
    return __uint_as_float(u);
}

// kth (0-based) smallest key among uv[0..NEL). Block-collective.
__device__ unsigned int radix_select(const unsigned int* uv, int k, int tid,
                                     int* hist, volatile unsigned int* sh2)
{
    unsigned int prefix = 0, pmask = 0;
    int kcur = k;
    for (int shift = 24; shift >= 0; shift -= 8) {
        for (int b = tid; b < 256; b += 512) hist[b] = 0;
        __syncthreads();
        for (int i = tid; i < NEL; i += 512) {
            unsigned int u = uv[i];
            if ((u & pmask) == prefix)
                atomicAdd(&hist[(u >> shift) & 255], 1);
        }
        __syncthreads();
        // warp 0: inclusive scan of 256 bins (8 bins/thread + warp scan)
        if (tid < 32) {
            int base = tid * 8;
            int loc[8];
            int s = 0;
#pragma unroll
            for (int j = 0; j < 8; j++) { s += hist[base + j]; loc[j] = s; }
            int incl = s;
#pragma unroll
            for (int o = 1; o < 32; o <<= 1) {
                int up = __shfl_up_sync(0xffffffffu, incl, o);
                if ((tid & 31) >= o) incl += up;
            }
            int excl = incl - s;
#pragma unroll
            for (int j = 0; j < 8; j++) hist[base + j] = loc[j] + excl;
        }
        __syncthreads();
        if (tid < 256) {
            int hi = hist[tid];
            int lo = tid ? hist[tid - 1] : 0;
            if (kcur >= lo && kcur < hi) { sh2[0] = (unsigned)tid; sh2[1] = (unsigned)lo; }
        }
        __syncthreads();
        unsigned int bin = sh2[0];
        kcur -= (int)sh2[1];
        prefix |= bin << shift;
        pmask  |= 255u << shift;
        __syncthreads();
    }
    return prefix;
}

__global__ __launch_bounds__(512) void robust_std_kernel()
{
    extern __shared__ unsigned int uv[];     // NEL keys = 48KB
    __shared__ int hist[256];
    __shared__ float sbuf[32];
    __shared__ volatile unsigned int sh2[2];

    const int arr = blockIdx.x;
    const int tid = threadIdx.x;
    const int T   = 512;
    const float* src = g_resid + (size_t)arr * NEL;

    for (int i = tid; i < NEL; i += T) {
        unsigned int u = __float_as_uint(src[i]);
        u = (u & 0x80000000u) ? ~u : (u | 0x80000000u);
        uv[i] = u;
    }
    __syncthreads();

    // ranks for jnp.quantile(q=0.15, 0.85), "linear" method, float32 math
    const float n1 = (float)(NEL - 1);
    float hlo = 0.15f * n1;  int ilo = (int)hlo;  float flo = hlo - (float)ilo;
    float hhi = 0.85f * n1;  int ihi = (int)hhi;  float fhi = hhi - (float)ihi;

    // next-rank value: v_{k+1} = vk if count(<=vk) >= k+2 else min{u > vk}
    auto next_val = [&](unsigned int vk, int k) -> unsigned int {
        float lc = 0.f;
        unsigned int lmin = 0xFFFFFFFFu;
        for (int i = tid; i < NEL; i += T) {
            unsigned int u = uv[i];
            if (u <= vk) lc += 1.f;
            else lmin = min(lmin, u);
        }
        float cle = blockSum512(lc, sbuf, tid);
        unsigned int mgt = blockMin512(lmin, (unsigned int*)sbuf, tid);
        return (cle >= (float)(k + 2)) ? vk : mgt;
    };

    unsigned int ulo0 = radix_select(uv, ilo, tid, hist, sh2);
    unsigned int ulo1 = next_val(ulo0, ilo);
    unsigned int uhi0 = radix_select(uv, ihi, tid, hist, sh2);
    unsigned int uhi1 = next_val(uhi0, ihi);

    float vlo0 = key_to_float(ulo0), vlo1 = key_to_float(ulo1);
    float vhi0 = key_to_float(uhi0), vhi1 = key_to_float(uhi1);
    float qlo = vlo0 + flo * (vlo1 - vlo0);
    float qhi = vhi0 + fhi * (vhi1 - vhi0);

    // Pass 1: quantile-outlier mask (Z_INDEX=0 -> thresholds are q themselves)
    float lc = 0.f, ls = 0.f;
    for (int i = tid; i < NEL; i += T) {
        float v = key_to_float(uv[i]);
        if (v < qlo || v > qhi) { lc += 1.f; ls += v; }
    }
    float cnt = blockSum512(lc, sbuf, tid);
    float sum = blockSum512(ls, sbuf, tid);

    int mode = 0;                 // 0=quantile mask, 1=simple mask, 2=all
    float muA = 0.f, sdA = 0.f;
    if (cnt < 0.5f) {
        float la = 0.f;
        for (int i = tid; i < NEL; i += T) la += key_to_float(uv[i]);
        float sumA = blockSum512(la, sbuf, tid);
        muA = sumA / (float)NEL;
        float lq = 0.f;
        for (int i = tid; i < NEL; i += T) {
            float d = key_to_float(uv[i]) - muA; lq += d * d;
        }
        float ssA = blockSum512(lq, sbuf, tid);
        sdA = sqrtf(ssA / (float)(NEL - 1));
        lc = 0.f; ls = 0.f;
        for (int i = tid; i < NEL; i += T) {
            float v = key_to_float(uv[i]);
            if (fabsf(v - muA) > sdA) { lc += 1.f; ls += v; }
        }
        cnt = blockSum512(lc, sbuf, tid);
        sum = blockSum512(ls, sbuf, tid);
        mode = 1;
        if (cnt < 0.5f) { mode = 2; cnt = (float)NEL; sum = sumA; }
    }

    float mean = sum / cnt;
    float lss = 0.f;
    for (int i = tid; i < NEL; i += T) {
        float v = key_to_float(uv[i]);
        bool w = (mode == 0) ? (v < qlo || v > qhi)
               : (mode == 1) ? (fabsf(v - muA) > sdA)
               : true;
        if (w) { float d = v - mean; lss += d * d; }
    }
    float ssd = blockSum512(lss, sbuf, tid);

    if (tid == 0)
        g_sigma[arr] = sqrtf(ssd / (cnt - 1.0f));
}

// ---------------------------------------------------------------------------
// Kernel C: out = mean_b max(sigma[2b], sigma[2b+1])
// ---------------------------------------------------------------------------
__global__ void finalize_kernel(float* __restrict__ out)
{
    int tid = threadIdx.x;                    // 32 threads
    float v = 0.f;
    if (tid < NB) v = fmaxf(g_sigma[2 * tid], g_sigma[2 * tid + 1]);
#pragma unroll
    for (int o = 16; o; o >>= 1) v += __shfl_down_sync(0xffffffffu, v, o);
    if (tid == 0) out[0] = v * (1.0f / (float)NB);
}

// ---------------------------------------------------------------------------
extern "C" void kernel_launch(void* const* d_in, const int* in_sizes, int n_in,
                              void* d_out, int out_size)
{
    const float* x = (const float*)d_in[0];
    const float* y = (const float*)d_in[1];
    float* out = (float*)d_out;
    (void)in_sizes; (void)n_in; (void)out_size;

    dim3 gridA(16, NARR);
    nn_resid_kernel<<<gridA, 128>>>(x, y);

    cudaFuncSetAttribute(robust_std_kernel,
                         cudaFuncAttributeMaxDynamicSharedMemorySize,
                         NEL * (int)sizeof(unsigned int));
    robust_std_kernel<<<NARR, 512, NEL * sizeof(unsigned int)>>>();

    finalize_kernel<<<1, 32>>>(out);
}

// round 3
// speedup vs baseline: 1.9612x; 1.1408x over previous
#include <cuda_runtime.h>
#include <math.h>

#define NPTS   4096
#define NB     16
#define NARR   32           // 16 batches x 2 directions
#define D      3
#define NEL    (NPTS * D)   // 12288 residual elements per array
#define TILE   2048         // targets per smem tile
#define NPAIR  (TILE / 2)
#define CPAIRS 16           // pairs per chunk
#define CT     (2 * CPAIRS) // 32 targets per chunk

// Scratch (device globals only; no allocation allowed)
__device__ float g_resid[(size_t)NARR * NEL];
__device__ float g_sigma[NARR];

// ---------------------------------------------------------------------------
// f32x2 packed helpers (sm_103a). Lane math bitwise == scalar fma.rn.f32.
// ---------------------------------------------------------------------------
__device__ __forceinline__ unsigned long long ffma2_u(
    unsigned long long a, unsigned long long b, unsigned long long c)
{
    unsigned long long d;
    asm("fma.rn.f32x2 %0, %1, %2, %3;" : "=l"(d) : "l"(a), "l"(b), "l"(c));
    return d;
}
__device__ __forceinline__ unsigned long long pack2(float lo, float hi)
{
    unsigned long long r;
    asm("mov.b64 %0, {%1, %2};" : "=l"(r) : "f"(lo), "f"(hi));
    return r;
}
__device__ __forceinline__ void unpack2(unsigned long long v, float& lo, float& hi)
{
    asm("mov.b64 {%0, %1}, %2;" : "=f"(lo), "=f"(hi) : "l"(v));
}

// Shared between tile-fill and rescan so the contraction is identical.
__device__ __forceinline__ float neg_half_norm(float x, float y, float z)
{
    return -0.5f * fmaf(x, x, fmaf(y, y, z * z));
}

// ---------------------------------------------------------------------------
// Kernel A: brute-force NN. Inner loop = pure max (no argmax tracking);
// winning 32-target chunk is rescanned at the end to recover the index.
// Maximize s = a.b - 0.5|b|^2  <=>  minimize |a-b|^2.
// ---------------------------------------------------------------------------
__global__ __launch_bounds__(128) void nn_resid_kernel(
    const float* __restrict__ x, const float* __restrict__ y)
{
    const int arr   = blockIdx.y;          // 0..31
    const int batch = arr >> 1;
    const int dir   = arr & 1;
    const float* Qp = (dir == 0) ? (x + (size_t)batch * NPTS * D)
                                 : (y + (size_t)batch * NPTS * D);
    const float* Tp = (dir == 0) ? (y + (size_t)batch * NPTS * D)
                                 : (x + (size_t)batch * NPTS * D);

    // pair-interleaved target tiles: sxy[p]={x0,x1,y0,y1}, szw[p]={z0,z1,w0,w1}
    __shared__ float4 sxy[NPAIR];
    __shared__ float4 szw[NPAIR];

    const int tid = threadIdx.x;           // 128 threads
    const int QN  = 2;
    const int qbase = blockIdx.x * (128 * QN);
    const float NEG_INF = __int_as_float(0xff800000);

    unsigned long long axx[QN], ayy[QN], azz[QN];
    float ax[QN], ay[QN], az[QN];
    float gbest[QN];
    int   gchunk[QN];
#pragma unroll
    for (int q = 0; q < QN; q++) {
        int qi = qbase + tid + q * 128;
        ax[q] = Qp[3 * qi + 0];
        ay[q] = Qp[3 * qi + 1];
        az[q] = Qp[3 * qi + 2];
        axx[q] = pack2(ax[q], ax[q]);
        ayy[q] = pack2(ay[q], ay[q]);
        azz[q] = pack2(az[q], az[q]);
        gbest[q]  = NEG_INF;
        gchunk[q] = 0;
    }

    for (int t = 0; t < NPTS; t += TILE) {
        __syncthreads();
        for (int p = tid; p < NPAIR; p += 128) {
            const float* p0 = Tp + 3 * (size_t)(t + 2 * p);
            float x0 = p0[0], y0 = p0[1], z0 = p0[2];
            float x1 = p0[3], y1 = p0[4], z1 = p0[5];
            sxy[p] = make_float4(x0, x1, y0, y1);
            szw[p] = make_float4(z0, z1,
                                 neg_half_norm(x0, y0, z0),
                                 neg_half_norm(x1, y1, z1));
        }
        __syncthreads();

        for (int c = 0; c < NPAIR; c += CPAIRS) {
            float clo[QN], chi[QN];
#pragma unroll
            for (int q = 0; q < QN; q++) { clo[q] = NEG_INF; chi[q] = NEG_INF; }
#pragma unroll
            for (int pp = 0; pp < CPAIRS; pp++) {
                int p = c + pp;
                float4 f0 = sxy[p];
                float4 f1 = szw[p];
                unsigned long long bxx = pack2(f0.x, f0.y);
                unsigned long long byy = pack2(f0.z, f0.w);
                unsigned long long bzz = pack2(f1.x, f1.y);
                unsigned long long bww = pack2(f1.z, f1.w);
#pragma unroll
                for (int q = 0; q < QN; q++) {
                    unsigned long long s2 =
                        ffma2_u(axx[q], bxx, ffma2_u(ayy[q], byy,
                                ffma2_u(azz[q], bzz, bww)));
                    float slo, shi;
                    unpack2(s2, slo, shi);
                    clo[q] = fmaxf(clo[q], slo);
                    chi[q] = fmaxf(chi[q], shi);
                }
            }
#pragma unroll
            for (int q = 0; q < QN; q++) {
                float cm = fmaxf(clo[q], chi[q]);
                if (cm > gbest[q]) { gbest[q] = cm; gchunk[q] = t + 2 * c; }
            }
        }
    }

    // Rescan winning chunk (32 targets) from global; bitwise-identical math.
#pragma unroll
    for (int q = 0; q < QN; q++) {
        int base = gchunk[q];
        int bi = -1;
        for (int i = 0; i < CT; i++) {
            const float* p = Tp + 3 * (size_t)(base + i);
            float bx = p[0], by = p[1], bz = p[2];
            float w = neg_half_norm(bx, by, bz);
            float s = fmaf(ax[q], bx, fmaf(ay[q], by, fmaf(az[q], bz, w)));
            if (bi < 0 && s == gbest[q]) bi = base + i;
        }
        if (bi < 0) bi = base;   // unreachable safety

        int qi = qbase + tid + q * 128;
        const float* p = Tp + 3 * (size_t)bi;
        float* r = g_resid + (size_t)arr * NEL + 3 * (size_t)qi;
        r[0] = ax[q] - p[0];
        r[1] = ay[q] - p[1];
        r[2] = az[q] - p[2];
    }
}

// ---------------------------------------------------------------------------
// Block reductions for 512 threads (16 warps)
// ---------------------------------------------------------------------------
__device__ __forceinline__ float blockSum512(float v, float* sb, int tid)
{
#pragma unroll
    for (int o = 16; o; o >>= 1) v += __shfl_down_sync(0xffffffffu, v, o);
    if ((tid & 31) == 0) sb[tid >> 5] = v;
    __syncthreads();
    if (tid < 32) {
        float w = (tid < 16) ? sb[tid] : 0.f;
#pragma unroll
        for (int o = 8; o; o >>= 1) w += __shfl_down_sync(0xffffffffu, w, o);
        if (tid == 0) sb[0] = w;
    }
    __syncthreads();
    float r = sb[0];
    __syncthreads();
    return r;
}

__device__ __forceinline__ unsigned int blockMin512(unsigned int v,
                                                    unsigned int* sb, int tid)
{
#pragma unroll
    for (int o = 16; o; o >>= 1)
        v = min(v, __shfl_down_sync(0xffffffffu, v, o));
    if ((tid & 31) == 0) sb[tid >> 5] = v;
    __syncthreads();
    if (tid < 32) {
        unsigned int w = (tid < 16) ? sb[tid] : 0xFFFFFFFFu;
#pragma unroll
        for (int o = 8; o; o >>= 1)
            w = min(w, __shfl_down_sync(0xffffffffu, w, o));
        if (tid == 0) sb[0] = w;
    }
    __syncthreads();
    unsigned int r = sb[0];
    __syncthreads();
    return r;
}

// ---------------------------------------------------------------------------
// Kernel B: per-array robust masked std via radix-select quantiles.
// ---------------------------------------------------------------------------
__device__ __forceinline__ float key_to_float(unsigned int u)
{
    u = (u & 0x80000000u) ? (u ^ 0x80000000u) : ~u;
    return __uint_as_float(u);
}

__device__ unsigned int radix_select(const unsigned int* uv, int k, int tid,
                                     int* hist, volatile unsigned int* sh2)
{
    unsigned int prefix = 0, pmask = 0;
    int kcur = k;
    for (int shift = 24; shift >= 0; shift -= 8) {
        for (int b = tid; b < 256; b += 512) hist[b] = 0;
        __syncthreads();
        for (int i = tid; i < NEL; i += 512) {
            unsigned int u = uv[i];
            if ((u & pmask) == prefix)
                atomicAdd(&hist[(u >> shift) & 255], 1);
        }
        __syncthreads();
        if (tid < 32) {
            int base = tid * 8;
            int loc[8];
            int s = 0;
#pragma unroll
            for (int j = 0; j < 8; j++) { s += hist[base + j]; loc[j] = s; }
            int incl = s;
#pragma unroll
            for (int o = 1; o < 32; o <<= 1) {
                int up = __shfl_up_sync(0xffffffffu, incl, o);
                if ((tid & 31) >= o) incl += up;
            }
            int excl = incl - s;
#pragma unroll
            for (int j = 0; j < 8; j++) hist[base + j] = loc[j] + excl;
        }
        __syncthreads();
        if (tid < 256) {
            int hi = hist[tid];
            int lo = tid ? hist[tid - 1] : 0;
            if (kcur >= lo && kcur < hi) { sh2[0] = (unsigned)tid; sh2[1] = (unsigned)lo; }
        }
        __syncthreads();
        unsigned int bin = sh2[0];
        kcur -= (int)sh2[1];
        prefix |= bin << shift;
        pmask  |= 255u << shift;
        __syncthreads();
    }
    return prefix;
}

__global__ __launch_bounds__(512) void robust_std_kernel()
{
    extern __shared__ unsigned int uv[];     // NEL keys = 48KB
    __shared__ int hist[256];
    __shared__ float sbuf[32];
    __shared__ volatile unsigned int sh2[2];

    const int arr = blockIdx.x;
    const int tid = threadIdx.x;
    const int T   = 512;
    const float* src = g_resid + (size_t)arr * NEL;

    for (int i = tid; i < NEL; i += T) {
        unsigned int u = __float_as_uint(src[i]);
        u = (u & 0x80000000u) ? ~u : (u | 0x80000000u);
        uv[i] = u;
    }
    __syncthreads();

    const float n1 = (float)(NEL - 1);
    float hlo = 0.15f * n1;  int ilo = (int)hlo;  float flo = hlo - (float)ilo;
    float hhi = 0.85f * n1;  int ihi = (int)hhi;  float fhi = hhi - (float)ihi;

    auto next_val = [&](unsigned int vk, int k) -> unsigned int {
        float lc = 0.f;
        unsigned int lmin = 0xFFFFFFFFu;
        for (int i = tid; i < NEL; i += T) {
            unsigned int u = uv[i];
            if (u <= vk) lc += 1.f;
            else lmin = min(lmin, u);
        }
        float cle = blockSum512(lc, sbuf, tid);
        unsigned int mgt = blockMin512(lmin, (unsigned int*)sbuf, tid);
        return (cle >= (float)(k + 2)) ? vk : mgt;
    };

    unsigned int ulo0 = radix_select(uv, ilo, tid, hist, sh2);
    unsigned int ulo1 = next_val(ulo0, ilo);
    unsigned int uhi0 = radix_select(uv, ihi, tid, hist, sh2);
    unsigned int uhi1 = next_val(uhi0, ihi);

    float vlo0 = key_to_float(ulo0), vlo1 = key_to_float(ulo1);
    float vhi0 = key_to_float(uhi0), vhi1 = key_to_float(uhi1);
    float qlo = vlo0 + flo * (vlo1 - vlo0);
    float qhi = vhi0 + fhi * (vhi1 - vhi0);

    float lc = 0.f, ls = 0.f;
    for (int i = tid; i < NEL; i += T) {
        float v = key_to_float(uv[i]);
        if (v < qlo || v > qhi) { lc += 1.f; ls += v; }
    }
    float cnt = blockSum512(lc, sbuf, tid);
    float sum = blockSum512(ls, sbuf, tid);

    int mode = 0;                 // 0=quantile mask, 1=simple mask, 2=all
    float muA = 0.f, sdA = 0.f;
    if (cnt < 0.5f) {
        float la = 0.f;
        for (int i = tid; i < NEL; i += T) la += key_to_float(uv[i]);
        float sumA = blockSum512(la, sbuf, tid);
        muA = sumA / (float)NEL;
        float lq = 0.f;
        for (int i = tid; i < NEL; i += T) {
            float d = key_to_float(uv[i]) - muA; lq += d * d;
        }
        float ssA = blockSum512(lq, sbuf, tid);
        sdA = sqrtf(ssA / (float)(NEL - 1));
        lc = 0.f; ls = 0.f;
        for (int i = tid; i < NEL; i += T) {
            float v = key_to_float(uv[i]);
            if (fabsf(v - muA) > sdA) { lc += 1.f; ls += v; }
        }
        cnt = blockSum512(lc, sbuf, tid);
        sum = blockSum512(ls, sbuf, tid);
        mode = 1;
        if (cnt < 0.5f) { mode = 2; cnt = (float)NEL; sum = sumA; }
    }

    float mean = sum / cnt;
    float lss = 0.f;
    for (int i = tid; i < NEL; i += T) {
        float v = key_to_float(uv[i]);
        bool w = (mode == 0) ? (v < qlo || v > qhi)
               : (mode == 1) ? (fabsf(v - muA) > sdA)
               : true;
        if (w) { float d = v - mean; lss += d * d; }
    }
    float ssd = blockSum512(lss, sbuf, tid);

    if (tid == 0)
        g_sigma[arr] = sqrtf(ssd / (cnt - 1.0f));
}

// ---------------------------------------------------------------------------
// Kernel C: out = mean_b max(sigma[2b], sigma[2b+1])
// ---------------------------------------------------------------------------
__global__ void finalize_kernel(float* __restrict__ out)
{
    int tid = threadIdx.x;                    // 32 threads
    float v = 0.f;
    if (tid < NB) v = fmaxf(g_sigma[2 * tid], g_sigma[2 * tid + 1]);
#pragma unroll
    for (int o = 16; o; o >>= 1) v += __shfl_down_sync(0xffffffffu, v, o);
    if (tid == 0) out[0] = v * (1.0f / (float)NB);
}

// ---------------------------------------------------------------------------
extern "C" void kernel_launch(void* const* d_in, const int* in_sizes, int n_in,
                              void* d_out, int out_size)
{
    const float* x = (const float*)d_in[0];
    const float* y = (const float*)d_in[1];
    float* out = (float*)d_out;
    (void)in_sizes; (void)n_in; (void)out_size;

    dim3 gridA(16, NARR);
    nn_resid_kernel<<<gridA, 128>>>(x, y);

    cudaFuncSetAttribute(robust_std_kernel,
                         cudaFuncAttributeMaxDynamicSharedMemorySize,
                         NEL * (int)sizeof(unsigned int));
    robust_std_kernel<<<NARR, 512, NEL * sizeof(unsigned int)>>>();

    finalize_kernel<<<1, 32>>>(out);
}